// round 1
// baseline (speedup 1.0000x reference)
#include <cuda_runtime.h>
#include <cstdint>

#define NUM_USERS 200000
#define NUM_ITEMS 100000
#define NUM_NODES (NUM_USERS + NUM_ITEMS)
#define EMBED_DIM 64
#define NUM_EDGES 2000000

// Scratch: layer-1 and layer-2 propagation outputs. Device globals (no alloc).
__device__ float g_x1[(size_t)NUM_NODES * EMBED_DIM];
__device__ float g_x2[(size_t)NUM_NODES * EMBED_DIM];

__device__ __forceinline__ void red_add_v4(float* p, float4 v) {
    asm volatile("red.global.add.v4.f32 [%0], {%1, %2, %3, %4};"
                 :: "l"(p), "f"(v.x), "f"(v.y), "f"(v.z), "f"(v.w)
                 : "memory");
}

// First-layer scatter: source rows come from the (logical) concat of u_embs / i_embs.
// 16 threads per edge; each thread handles one float4 chunk of the 64-dim row.
__global__ void scatter_layer1(const float* __restrict__ u_embs,
                               const float* __restrict__ i_embs,
                               const int* __restrict__ edge_src,
                               const int* __restrict__ edge_dst,
                               const float* __restrict__ edge_weight,
                               float* __restrict__ out) {
    long long gid = (long long)blockIdx.x * blockDim.x + threadIdx.x;
    int e = (int)(gid >> 4);
    int c = (int)(gid & 15);
    if (e >= NUM_EDGES) return;

    int s = __ldg(edge_src + e);
    int d = __ldg(edge_dst + e);
    float w = __ldg(edge_weight + e);

    const float* src_row = (s < NUM_USERS)
        ? (u_embs + (size_t)s * EMBED_DIM)
        : (i_embs + (size_t)(s - NUM_USERS) * EMBED_DIM);

    float4 v = *(const float4*)(src_row + c * 4);
    v.x *= w; v.y *= w; v.z *= w; v.w *= w;
    red_add_v4(out + (size_t)d * EMBED_DIM + c * 4, v);
}

// Second-layer scatter: source rows come from g_x1.
__global__ void scatter_layer2(const int* __restrict__ edge_src,
                               const int* __restrict__ edge_dst,
                               const float* __restrict__ edge_weight,
                               const float* __restrict__ xin,
                               float* __restrict__ out) {
    long long gid = (long long)blockIdx.x * blockDim.x + threadIdx.x;
    int e = (int)(gid >> 4);
    int c = (int)(gid & 15);
    if (e >= NUM_EDGES) return;

    int s = __ldg(edge_src + e);
    int d = __ldg(edge_dst + e);
    float w = __ldg(edge_weight + e);

    float4 v = *(const float4*)(xin + (size_t)s * EMBED_DIM + c * 4);
    v.x *= w; v.y *= w; v.z *= w; v.w *= w;
    red_add_v4(out + (size_t)d * EMBED_DIM + c * 4, v);
}

// out = (x0 + x1 + x2) / 3, fully coalesced float4 streaming.
__global__ void finalize_kernel(const float* __restrict__ u_embs,
                                const float* __restrict__ i_embs,
                                const float* __restrict__ x1,
                                const float* __restrict__ x2,
                                float* __restrict__ out) {
    long long gid = (long long)blockIdx.x * blockDim.x + threadIdx.x;
    long long total = (long long)NUM_NODES * (EMBED_DIM / 4);
    if (gid >= total) return;

    int n = (int)(gid >> 4);       // node
    int c = (int)(gid & 15);       // float4 chunk

    const float* x0_row = (n < NUM_USERS)
        ? (u_embs + (size_t)n * EMBED_DIM)
        : (i_embs + (size_t)(n - NUM_USERS) * EMBED_DIM);

    float4 a = *(const float4*)(x0_row + c * 4);
    float4 b = *(const float4*)(x1 + (size_t)n * EMBED_DIM + c * 4);
    float4 d = *(const float4*)(x2 + (size_t)n * EMBED_DIM + c * 4);

    const float inv3 = 1.0f / 3.0f;
    float4 r;
    r.x = (a.x + b.x + d.x) * inv3;
    r.y = (a.y + b.y + d.y) * inv3;
    r.z = (a.z + b.z + d.z) * inv3;
    r.w = (a.w + b.w + d.w) * inv3;

    *(float4*)(out + (size_t)n * EMBED_DIM + c * 4) = r;
}

extern "C" void kernel_launch(void* const* d_in, const int* in_sizes, int n_in,
                              void* d_out, int out_size) {
    const float* u_embs      = (const float*)d_in[0];
    const float* i_embs      = (const float*)d_in[1];
    const int*   edge_src    = (const int*)d_in[2];
    const int*   edge_dst    = (const int*)d_in[3];
    const float* edge_weight = (const float*)d_in[4];
    float* out = (float*)d_out;

    void* x1_ptr = nullptr;
    void* x2_ptr = nullptr;
    cudaGetSymbolAddress(&x1_ptr, g_x1);
    cudaGetSymbolAddress(&x2_ptr, g_x2);
    float* x1 = (float*)x1_ptr;
    float* x2 = (float*)x2_ptr;

    size_t scratch_bytes = (size_t)NUM_NODES * EMBED_DIM * sizeof(float);
    cudaMemsetAsync(x1, 0, scratch_bytes, 0);
    cudaMemsetAsync(x2, 0, scratch_bytes, 0);

    // Scatter layer 1: E * 16 threads
    {
        long long total = (long long)NUM_EDGES * 16;
        int threads = 256;
        int blocks = (int)((total + threads - 1) / threads);
        scatter_layer1<<<blocks, threads>>>(u_embs, i_embs, edge_src, edge_dst,
                                            edge_weight, x1);
    }

    // Scatter layer 2
    {
        long long total = (long long)NUM_EDGES * 16;
        int threads = 256;
        int blocks = (int)((total + threads - 1) / threads);
        scatter_layer2<<<blocks, threads>>>(edge_src, edge_dst, edge_weight,
                                            x1, x2);
    }

    // Finalize
    {
        long long total = (long long)NUM_NODES * (EMBED_DIM / 4);
        int threads = 256;
        int blocks = (int)((total + threads - 1) / threads);
        finalize_kernel<<<blocks, threads>>>(u_embs, i_embs, x1, x2, out);
    }
}

// round 2
// speedup vs baseline: 1.7379x; 1.7379x over previous
#include <cuda_runtime.h>
#include <cstdint>

#define NUM_USERS 200000
#define NUM_ITEMS 100000
#define NUM_NODES (NUM_USERS + NUM_ITEMS)
#define EMBED_DIM 64
#define NUM_EDGES 2000000

#define SCAN_CHUNK 1024
#define NUM_SCAN_BLOCKS ((NUM_NODES + SCAN_CHUNK - 1) / SCAN_CHUNK)  // 293

// ---- device-global scratch (no allocation allowed) ----
__device__ int   g_deg[NUM_NODES];
__device__ int   g_off[NUM_NODES + 1];
__device__ int   g_pos[NUM_NODES];
__device__ int   g_bsum[512];
__device__ int   g_ssrc[NUM_EDGES];
__device__ float g_sw[NUM_EDGES];
__device__ float g_x1[(size_t)NUM_NODES * EMBED_DIM];

// ---- 1. histogram of dst degrees ----
__global__ void hist_kernel(const int* __restrict__ edge_dst) {
    int e = blockIdx.x * blockDim.x + threadIdx.x;
    if (e >= NUM_EDGES) return;
    atomicAdd(&g_deg[__ldg(edge_dst + e)], 1);   // no return -> RED
}

// ---- 2a. per-chunk sums ----
__global__ void block_sum_kernel() {
    __shared__ int s[SCAN_CHUNK];
    int t = threadIdx.x;
    int idx = blockIdx.x * SCAN_CHUNK + t;
    s[t] = (idx < NUM_NODES) ? g_deg[idx] : 0;
    __syncthreads();
    for (int o = SCAN_CHUNK / 2; o > 0; o >>= 1) {
        if (t < o) s[t] += s[t + o];
        __syncthreads();
    }
    if (t == 0) g_bsum[blockIdx.x] = s[0];
}

// ---- 2b. scan chunk sums (single block) ----
__global__ void scan_bsum_kernel() {
    __shared__ int s[512];
    int t = threadIdx.x;
    int v = (t < NUM_SCAN_BLOCKS) ? g_bsum[t] : 0;
    s[t] = v;
    __syncthreads();
    for (int o = 1; o < 512; o <<= 1) {
        int x = (t >= o) ? s[t - o] : 0;
        __syncthreads();
        s[t] += x;
        __syncthreads();
    }
    if (t < NUM_SCAN_BLOCKS) g_bsum[t] = s[t] - v;  // exclusive
}

// ---- 2c. per-chunk exclusive scan + add chunk base -> offsets & cursors ----
__global__ void offsets_kernel() {
    __shared__ int s[SCAN_CHUNK];
    int t = threadIdx.x;
    int idx = blockIdx.x * SCAN_CHUNK + t;
    int v = (idx < NUM_NODES) ? g_deg[idx] : 0;
    s[t] = v;
    __syncthreads();
    for (int o = 1; o < SCAN_CHUNK; o <<= 1) {
        int x = (t >= o) ? s[t - o] : 0;
        __syncthreads();
        s[t] += x;
        __syncthreads();
    }
    int excl = s[t] - v + g_bsum[blockIdx.x];
    if (idx < NUM_NODES) {
        g_off[idx] = excl;
        g_pos[idx] = excl;
        if (idx == NUM_NODES - 1) g_off[NUM_NODES] = excl + v;
    }
}

// ---- 3. bucket edges by dst ----
__global__ void bucket_kernel(const int* __restrict__ edge_src,
                              const int* __restrict__ edge_dst,
                              const float* __restrict__ edge_weight) {
    int e = blockIdx.x * blockDim.x + threadIdx.x;
    if (e >= NUM_EDGES) return;
    int d = __ldg(edge_dst + e);
    int p = atomicAdd(&g_pos[d], 1);
    g_ssrc[p] = __ldg(edge_src + e);
    g_sw[p]   = __ldg(edge_weight + e);
}

// ---- 4. layer-1 gather: x1[n] = sum_{e in CSR[n]} w_e * x0[src_e] ----
// 16 threads per node; each thread owns one float4 column chunk.
__global__ void gather1_kernel(const float* __restrict__ u_embs,
                               const float* __restrict__ i_embs) {
    long long gid = (long long)blockIdx.x * blockDim.x + threadIdx.x;
    int n = (int)(gid >> 4);
    int c = (int)(gid & 15);
    if (n >= NUM_NODES) return;

    int b = __ldg(&g_off[n]);
    int e = __ldg(&g_off[n + 1]);
    float4 acc = make_float4(0.f, 0.f, 0.f, 0.f);

    int k = b;
    for (; k + 1 < e; k += 2) {
        int s0 = __ldg(&g_ssrc[k]);     float w0 = __ldg(&g_sw[k]);
        int s1 = __ldg(&g_ssrc[k + 1]); float w1 = __ldg(&g_sw[k + 1]);
        const float* r0 = (s0 < NUM_USERS) ? (u_embs + (size_t)s0 * EMBED_DIM)
                                           : (i_embs + (size_t)(s0 - NUM_USERS) * EMBED_DIM);
        const float* r1 = (s1 < NUM_USERS) ? (u_embs + (size_t)s1 * EMBED_DIM)
                                           : (i_embs + (size_t)(s1 - NUM_USERS) * EMBED_DIM);
        float4 v0 = *(const float4*)(r0 + c * 4);
        float4 v1 = *(const float4*)(r1 + c * 4);
        acc.x += w0 * v0.x + w1 * v1.x;
        acc.y += w0 * v0.y + w1 * v1.y;
        acc.z += w0 * v0.z + w1 * v1.z;
        acc.w += w0 * v0.w + w1 * v1.w;
    }
    if (k < e) {
        int s0 = __ldg(&g_ssrc[k]); float w0 = __ldg(&g_sw[k]);
        const float* r0 = (s0 < NUM_USERS) ? (u_embs + (size_t)s0 * EMBED_DIM)
                                           : (i_embs + (size_t)(s0 - NUM_USERS) * EMBED_DIM);
        float4 v0 = *(const float4*)(r0 + c * 4);
        acc.x += w0 * v0.x; acc.y += w0 * v0.y;
        acc.z += w0 * v0.z; acc.w += w0 * v0.w;
    }
    *(float4*)(g_x1 + (size_t)n * EMBED_DIM + c * 4) = acc;
}

// ---- 5. layer-2 gather fused with finalize: out[n] = (x0[n] + x1[n] + x2[n]) / 3 ----
__global__ void gather2_fin_kernel(const float* __restrict__ u_embs,
                                   const float* __restrict__ i_embs,
                                   float* __restrict__ out) {
    long long gid = (long long)blockIdx.x * blockDim.x + threadIdx.x;
    int n = (int)(gid >> 4);
    int c = (int)(gid & 15);
    if (n >= NUM_NODES) return;

    int b = __ldg(&g_off[n]);
    int e = __ldg(&g_off[n + 1]);
    float4 acc = make_float4(0.f, 0.f, 0.f, 0.f);

    int k = b;
    for (; k + 1 < e; k += 2) {
        int s0 = __ldg(&g_ssrc[k]);     float w0 = __ldg(&g_sw[k]);
        int s1 = __ldg(&g_ssrc[k + 1]); float w1 = __ldg(&g_sw[k + 1]);
        float4 v0 = *(const float4*)(g_x1 + (size_t)s0 * EMBED_DIM + c * 4);
        float4 v1 = *(const float4*)(g_x1 + (size_t)s1 * EMBED_DIM + c * 4);
        acc.x += w0 * v0.x + w1 * v1.x;
        acc.y += w0 * v0.y + w1 * v1.y;
        acc.z += w0 * v0.z + w1 * v1.z;
        acc.w += w0 * v0.w + w1 * v1.w;
    }
    if (k < e) {
        int s0 = __ldg(&g_ssrc[k]); float w0 = __ldg(&g_sw[k]);
        float4 v0 = *(const float4*)(g_x1 + (size_t)s0 * EMBED_DIM + c * 4);
        acc.x += w0 * v0.x; acc.y += w0 * v0.y;
        acc.z += w0 * v0.z; acc.w += w0 * v0.w;
    }

    const float* x0_row = (n < NUM_USERS) ? (u_embs + (size_t)n * EMBED_DIM)
                                          : (i_embs + (size_t)(n - NUM_USERS) * EMBED_DIM);
    float4 a  = *(const float4*)(x0_row + c * 4);
    float4 b1 = *(const float4*)(g_x1 + (size_t)n * EMBED_DIM + c * 4);

    const float inv3 = 1.0f / 3.0f;
    float4 r;
    r.x = (a.x + b1.x + acc.x) * inv3;
    r.y = (a.y + b1.y + acc.y) * inv3;
    r.z = (a.z + b1.z + acc.z) * inv3;
    r.w = (a.w + b1.w + acc.w) * inv3;
    *(float4*)(out + (size_t)n * EMBED_DIM + c * 4) = r;
}

extern "C" void kernel_launch(void* const* d_in, const int* in_sizes, int n_in,
                              void* d_out, int out_size) {
    const float* u_embs      = (const float*)d_in[0];
    const float* i_embs      = (const float*)d_in[1];
    const int*   edge_src    = (const int*)d_in[2];
    const int*   edge_dst    = (const int*)d_in[3];
    const float* edge_weight = (const float*)d_in[4];
    float* out = (float*)d_out;

    void* deg_ptr = nullptr;
    cudaGetSymbolAddress(&deg_ptr, g_deg);
    cudaMemsetAsync(deg_ptr, 0, NUM_NODES * sizeof(int), 0);

    // histogram
    hist_kernel<<<(NUM_EDGES + 255) / 256, 256>>>(edge_dst);

    // prefix scan of degrees -> offsets + cursors
    block_sum_kernel<<<NUM_SCAN_BLOCKS, SCAN_CHUNK>>>();
    scan_bsum_kernel<<<1, 512>>>();
    offsets_kernel<<<NUM_SCAN_BLOCKS, SCAN_CHUNK>>>();

    // bucket edges by dst
    bucket_kernel<<<(NUM_EDGES + 255) / 256, 256>>>(edge_src, edge_dst, edge_weight);

    // layer 1 gather
    {
        long long total = (long long)NUM_NODES * 16;
        int threads = 256;
        int blocks = (int)((total + threads - 1) / threads);
        gather1_kernel<<<blocks, threads>>>(u_embs, i_embs);
    }

    // layer 2 gather + finalize
    {
        long long total = (long long)NUM_NODES * 16;
        int threads = 256;
        int blocks = (int)((total + threads - 1) / threads);
        gather2_fin_kernel<<<blocks, threads>>>(u_embs, i_embs, out);
    }
}